// round 6
// baseline (speedup 1.0000x reference)
#include <cuda_runtime.h>
#include <cuda_fp16.h>
#include <cstdint>

// ---------------- problem constants ----------------
#define BATCH 32
#define CIN   512
#define COUT  512
#define QL    4096
#define LPAD  4098          // 1 zero row of padding at each end (conv pad=1)

// GEMM tiling: CTA 128x128, 4 warps of 64x64, 2 CTAs/SM
#define TILE_M 128
#define TILE_N 128
#define TILE_K 64           // c per chunk (128B fp16 rows, swizzled)
#define NCHUNK 24           // 3 taps * (512/64)
#define NSTAGE 3
#define STAGE_BYTES 32768   // A 16KB + B 16KB
#define A_OFF 0
#define B_OFF 16384
#define SMEM_DYN (NSTAGE * STAGE_BYTES)

// ---------------- device scratch ----------------
__device__ __align__(16) __half g_qx[(size_t)BATCH * LPAD * CIN];   // [b][l+1][c] quantized x (exact ints)
__device__ __align__(16) __half g_w2[(size_t)3 * COUT * CIN];       // [k][o][c]  w'' = qw*sw*sa (fp16)

// ---------------- base-ISA helpers ----------------
__device__ __forceinline__ uint32_t smem_u32(const void* p) {
    uint32_t a;
    asm("{ .reg .u64 t; cvta.to.shared.u64 t, %1; cvt.u32.u64 %0, t; }" : "=r"(a) : "l"(p));
    return a;
}
#define SWU(u, r) (((u) ^ ((r) & 7)) << 4)   // 16B-unit swizzle within a 128B row

__device__ __forceinline__ void cp_async16(uint32_t saddr, const void* gptr) {
    asm volatile("cp.async.cg.shared.global [%0], [%1], 16;" :: "r"(saddr), "l"(gptr));
}
#define CP_COMMIT() asm volatile("cp.async.commit_group;" ::: "memory")
#define CP_WAIT(n)  asm volatile("cp.async.wait_group %0;" :: "n"(n) : "memory")

__device__ __forceinline__ void ldm_x4(uint32_t& r0, uint32_t& r1, uint32_t& r2, uint32_t& r3, uint32_t a) {
    asm volatile("ldmatrix.sync.aligned.m8n8.x4.shared.b16 {%0,%1,%2,%3}, [%4];"
                 : "=r"(r0), "=r"(r1), "=r"(r2), "=r"(r3) : "r"(a));
}
__device__ __forceinline__ void mma16816(float& c0, float& c1, float& c2, float& c3,
                                         uint32_t a0, uint32_t a1, uint32_t a2, uint32_t a3,
                                         uint32_t b0, uint32_t b1) {
    asm("mma.sync.aligned.m16n8k16.row.col.f32.f16.f16.f32 "
        "{%0,%1,%2,%3}, {%4,%5,%6,%7}, {%8,%9}, {%0,%1,%2,%3};"
        : "+f"(c0), "+f"(c1), "+f"(c2), "+f"(c3)
        : "r"(a0), "r"(a1), "r"(a2), "r"(a3), "r"(b0), "r"(b1));
}

// ---------------- kernel 1: weight prep ----------------
// w'' = clip(rint(w/sw))*sw*sa, fp16; layout [k][o][c]
__global__ void prep_w_kernel(const float* __restrict__ w,
                              const float* __restrict__ a_scale,
                              const float* __restrict__ w_scale) {
    int o = blockIdx.x, c = threadIdx.x;
    float sw = fabsf(w_scale[o]) + 1e-8f;
    float sa = fabsf(a_scale[c]) + 1e-8f;
#pragma unroll
    for (int k = 0; k < 3; k++) {
        float v = w[((size_t)o * CIN + c) * 3 + k];
        float q = fminf(fmaxf(rintf(v / sw), -128.f), 127.f);
        float wpp = (q * sw) * sa;
        g_w2[((size_t)k * COUT + o) * CIN + c] = __float2half_rn(wpp);
    }
}

// ---------------- kernel 2: zero pad rows ----------------
__global__ void pad_kernel() {
    int b = blockIdx.x, c = threadIdx.x;
    g_qx[((size_t)b * LPAD + 0) * CIN + c]          = __float2half_rn(0.f);
    g_qx[((size_t)b * LPAD + (LPAD - 1)) * CIN + c] = __float2half_rn(0.f);
}

// ---------------- kernel 3: quantize + transpose x -> g_qx[b][l+1][c] ----------------
__global__ void quant_kernel(const float* __restrict__ x, const float* __restrict__ a_scale) {
    __shared__ __half tile[32][33];
    int tx = threadIdx.x, ty = threadIdx.y;
    int l0 = blockIdx.x * 32, c0 = blockIdx.y * 32, b = blockIdx.z;
#pragma unroll
    for (int j = 0; j < 4; j++) {
        int c = c0 + ty + j * 8;
        float s = fabsf(a_scale[c]) + 1e-8f;
        float v = x[((size_t)b * CIN + c) * QL + l0 + tx];
        float q = fminf(fmaxf(rintf(v / s), -128.f), 127.f);
        tile[ty + j * 8][tx] = __float2half_rn(q);   // integer, exact in fp16
    }
    __syncthreads();
#pragma unroll
    for (int j = 0; j < 4; j++) {
        int l = l0 + ty + j * 8;
        g_qx[((size_t)b * LPAD + l + 1) * CIN + c0 + tx] = tile[tx][ty + j * 8];
    }
}

// ---------------- kernel 4: 3-stage pipelined mma.sync GEMM-conv ----------------
// 4 warps, warp tile 64x64, 2 CTAs/SM
// out[b, o0+m, L0+n] = sum over (k, c) of qx[b, L0+n+k-1, c] * w''[o0+m, c, k]  (+bias)
__global__ void __launch_bounds__(128, 2)
qconv_gemm(const float* __restrict__ bias, float* __restrict__ out) {
    extern __shared__ __align__(16) char smem[];
    const uint32_t sbase = smem_u32(smem);
    const int tid  = threadIdx.x;
    const int wid  = tid >> 5;
    const int lane = tid & 31;
    const int L0 = blockIdx.x * TILE_N;
    const int o0 = blockIdx.y * TILE_M;
    const int b  = blockIdx.z;

    // warp tile: 64(m) x 64(n); warp grid 2(m) x 2(n)
    const int wm = (wid & 1) * 64;
    const int wn = (wid >> 1) * 64;

    const uint4* gw = reinterpret_cast<const uint4*>(g_w2);
    const uint4* gx = reinterpret_cast<const uint4*>(g_qx);

    // ---- async tile loader: 16B per cp.async, swizzled; 128 threads ----
    auto load_chunk = [&](int chunk, int stage) {
        const int k  = chunk >> 3;      // tap 0..2
        const int cc = chunk & 7;       // c-chunk 0..7
        const uint32_t sb = sbase + stage * STAGE_BYTES;
        // A tile: 128 rows x 8 units -> 1024 units, 8 per thread
#pragma unroll
        for (int j = 0; j < 8; j++) {
            int e = tid + j * 128;
            int r = e >> 3, u = e & 7;
            uint32_t so = (uint32_t)(r * 128) + SWU(u, r);
            cp_async16(sb + A_OFF + so, &gw[(size_t)(k * COUT + o0 + r) * 64 + cc * 8 + u]);
        }
        // B tile: 128 rows x 8 units -> 1024 units, 8 per thread
#pragma unroll
        for (int j = 0; j < 8; j++) {
            int e = tid + j * 128;
            int r = e >> 3, u = e & 7;
            uint32_t so = (uint32_t)(r * 128) + SWU(u, r);
            cp_async16(sb + B_OFF + so, &gx[((size_t)b * LPAD + L0 + k + r) * 64 + cc * 8 + u]);
        }
    };

    float acc[4][8][4];
#pragma unroll
    for (int mi = 0; mi < 4; mi++)
#pragma unroll
        for (int nj = 0; nj < 8; nj++)
#pragma unroll
            for (int q = 0; q < 4; q++) acc[mi][nj][q] = 0.f;

    // prologue: 2 stages in flight
    load_chunk(0, 0); CP_COMMIT();
    load_chunk(1, 1); CP_COMMIT();

    // ldmatrix lane addressing
    const int lrow = (lane & 7) + ((lane >> 3) & 1) * 8;   // row within 16-row block
    const int lcol = (lane >> 4);                          // 0/1 -> +16B (k+8)

    for (int i = 0; i < NCHUNK; i++) {
        CP_WAIT(1);                    // chunk i resident; chunk i+1 may still be in flight
        __syncthreads();
        if (i + 2 < NCHUNK) { load_chunk(i + 2, (i + 2) % NSTAGE); CP_COMMIT(); }

        const uint32_t sb = sbase + (i % NSTAGE) * STAGE_BYTES;
#pragma unroll
        for (int ks = 0; ks < 4; ks++) {
            // B fragments: 4 x ldmatrix.x4 covering 64 n x 16 k
            uint32_t bf[4][4];
#pragma unroll
            for (int t = 0; t < 4; t++) {
                int r = wn + t * 16 + lrow;
                int u = ks * 2 + lcol;
                ldm_x4(bf[t][0], bf[t][1], bf[t][2], bf[t][3],
                       sb + B_OFF + r * 128 + SWU(u, r));
            }
            // A fragments: 4 x ldmatrix.x4 covering 64 m x 16 k
            uint32_t af[4][4];
#pragma unroll
            for (int t = 0; t < 4; t++) {
                int r = wm + t * 16 + lrow;
                int u = ks * 2 + lcol;
                ldm_x4(af[t][0], af[t][1], af[t][2], af[t][3],
                       sb + A_OFF + r * 128 + SWU(u, r));
            }
#pragma unroll
            for (int mi = 0; mi < 4; mi++)
#pragma unroll
                for (int t = 0; t < 4; t++) {
                    mma16816(acc[mi][t*2  ][0], acc[mi][t*2  ][1], acc[mi][t*2  ][2], acc[mi][t*2  ][3],
                             af[mi][0], af[mi][1], af[mi][2], af[mi][3], bf[t][0], bf[t][2]);
                    mma16816(acc[mi][t*2+1][0], acc[mi][t*2+1][1], acc[mi][t*2+1][2], acc[mi][t*2+1][3],
                             af[mi][0], af[mi][1], af[mi][2], af[mi][3], bf[t][1], bf[t][3]);
                }
        }
    }

    // ---- epilogue: bias + store ----
#pragma unroll
    for (int mi = 0; mi < 4; mi++) {
        int r0 = wm + mi * 16 + (lane >> 2);
        int o_a = o0 + r0, o_b = o0 + r0 + 8;
        float bv0 = bias[o_a], bv1 = bias[o_b];
        float* pa = out + ((size_t)b * COUT + o_a) * QL + L0;
        float* pb = out + ((size_t)b * COUT + o_b) * QL + L0;
#pragma unroll
        for (int nj = 0; nj < 8; nj++) {
            int col = wn + nj * 8 + (lane & 3) * 2;
            float2 v0 = make_float2(acc[mi][nj][0] + bv0, acc[mi][nj][1] + bv0);
            float2 v1 = make_float2(acc[mi][nj][2] + bv1, acc[mi][nj][3] + bv1);
            *reinterpret_cast<float2*>(pa + col) = v0;
            *reinterpret_cast<float2*>(pb + col) = v1;
        }
    }
}

// ---------------- launch ----------------
extern "C" void kernel_launch(void* const* d_in, const int* in_sizes, int n_in,
                              void* d_out, int out_size) {
    (void)in_sizes; (void)n_in; (void)out_size;
    const float* x       = (const float*)d_in[0];
    const float* weight  = (const float*)d_in[1];
    const float* bias    = (const float*)d_in[2];
    const float* a_scale = (const float*)d_in[3];
    const float* w_scale = (const float*)d_in[4];
    float* out = (float*)d_out;

    prep_w_kernel<<<COUT, CIN>>>(weight, a_scale, w_scale);
    pad_kernel<<<BATCH, CIN>>>();
    quant_kernel<<<dim3(QL / 32, CIN / 32, BATCH), dim3(32, 8)>>>(x, a_scale);

    cudaFuncSetAttribute(qconv_gemm, cudaFuncAttributeMaxDynamicSharedMemorySize, SMEM_DYN);
    qconv_gemm<<<dim3(QL / TILE_N, COUT / TILE_M, BATCH), 128, SMEM_DYN>>>(bias, out);
}

// round 7
// speedup vs baseline: 1.0756x; 1.0756x over previous
#include <cuda_runtime.h>
#include <cuda_fp16.h>
#include <cstdint>

// ---------------- problem constants ----------------
#define BATCH 32
#define CIN   512
#define COUT  512
#define QL    4096
#define LPAD  4098          // 1 zero row of padding at each end (conv pad=1)

// GEMM tiling (round-4 best: 256 thr, 8 warps of 32x64, 2 CTAs/SM)
#define TILE_M 128
#define TILE_N 128
#define TILE_K 64           // c per chunk (128B fp16 rows, swizzled)
#define NCHUNK 24           // 3 taps * (512/64)
#define NSTAGE 3
#define STAGE_BYTES 32768   // A 16KB + B 16KB
#define A_OFF 0
#define B_OFF 16384
#define SMEM_DYN (NSTAGE * STAGE_BYTES)

// ---------------- device scratch ----------------
__device__ __align__(16) __half g_qx[(size_t)BATCH * LPAD * CIN];   // [b][l+1][c] quantized x (exact ints)
__device__ __align__(16) __half g_w2[(size_t)3 * COUT * CIN];       // [k][o][c]  w'' = qw*sw*sa (fp16)

// ---------------- base-ISA helpers ----------------
__device__ __forceinline__ uint32_t smem_u32(const void* p) {
    uint32_t a;
    asm("{ .reg .u64 t; cvta.to.shared.u64 t, %1; cvt.u32.u64 %0, t; }" : "=r"(a) : "l"(p));
    return a;
}
#define SWU(u, r) (((u) ^ ((r) & 7)) << 4)   // 16B-unit swizzle within a 128B row

__device__ __forceinline__ void cp_async16(uint32_t saddr, const void* gptr) {
    asm volatile("cp.async.cg.shared.global [%0], [%1], 16;" :: "r"(saddr), "l"(gptr));
}
#define CP_COMMIT() asm volatile("cp.async.commit_group;" ::: "memory")
#define CP_WAIT(n)  asm volatile("cp.async.wait_group %0;" :: "n"(n) : "memory")

__device__ __forceinline__ void ldm_x4(uint32_t& r0, uint32_t& r1, uint32_t& r2, uint32_t& r3, uint32_t a) {
    asm volatile("ldmatrix.sync.aligned.m8n8.x4.shared.b16 {%0,%1,%2,%3}, [%4];"
                 : "=r"(r0), "=r"(r1), "=r"(r2), "=r"(r3) : "r"(a));
}
__device__ __forceinline__ void mma16816(float& c0, float& c1, float& c2, float& c3,
                                         uint32_t a0, uint32_t a1, uint32_t a2, uint32_t a3,
                                         uint32_t b0, uint32_t b1) {
    asm("mma.sync.aligned.m16n8k16.row.col.f32.f16.f16.f32 "
        "{%0,%1,%2,%3}, {%4,%5,%6,%7}, {%8,%9}, {%0,%1,%2,%3};"
        : "+f"(c0), "+f"(c1), "+f"(c2), "+f"(c3)
        : "r"(a0), "r"(a1), "r"(a2), "r"(a3), "r"(b0), "r"(b1));
}

// ---------------- kernel 1: weight prep ----------------
// w'' = clip(rint(w/sw))*sw*sa, fp16; layout [k][o][c]
__global__ void prep_w_kernel(const float* __restrict__ w,
                              const float* __restrict__ a_scale,
                              const float* __restrict__ w_scale) {
    int o = blockIdx.x, c = threadIdx.x;
    float sw = fabsf(w_scale[o]) + 1e-8f;
    float sa = fabsf(a_scale[c]) + 1e-8f;
#pragma unroll
    for (int k = 0; k < 3; k++) {
        float v = w[((size_t)o * CIN + c) * 3 + k];
        float q = fminf(fmaxf(rintf(v / sw), -128.f), 127.f);
        float wpp = (q * sw) * sa;
        g_w2[((size_t)k * COUT + o) * CIN + c] = __float2half_rn(wpp);
    }
}

// ---------------- kernel 2: zero pad rows ----------------
__global__ void pad_kernel() {
    int b = blockIdx.x, c = threadIdx.x;
    g_qx[((size_t)b * LPAD + 0) * CIN + c]          = __float2half_rn(0.f);
    g_qx[((size_t)b * LPAD + (LPAD - 1)) * CIN + c] = __float2half_rn(0.f);
}

// ---------------- kernel 3: quantize + transpose x -> g_qx[b][l+1][c] ----------------
// 256 threads; tile = 64 l x 128 c. Coalesced float2 reads, smem transpose,
// uint2 (4-channel) coalesced stores.
__global__ void __launch_bounds__(256)
quant_kernel(const float* __restrict__ x, const float* __restrict__ a_scale) {
    __shared__ __half tile[128][66];          // [c_local][l_local], pad 2 halfs
    const int tid  = threadIdx.x;
    const int warp = tid >> 5;
    const int lane = tid & 31;
    const int l0 = blockIdx.x * 64;
    const int c0 = blockIdx.y * 128;
    const int b  = blockIdx.z;

    // read phase: each warp reads one c-row of 64 l (256B) per j
#pragma unroll
    for (int j = 0; j < 16; j++) {
        int ci = j * 8 + warp;
        float s = fabsf(a_scale[c0 + ci]) + 1e-8f;
        float2 v = *reinterpret_cast<const float2*>(
            &x[((size_t)b * CIN + c0 + ci) * QL + l0 + lane * 2]);
        float q0 = fminf(fmaxf(rintf(v.x / s), -128.f), 127.f);
        float q1 = fminf(fmaxf(rintf(v.y / s), -128.f), 127.f);
        *reinterpret_cast<half2*>(&tile[ci][lane * 2]) = __floats2half2_rn(q0, q1);
    }
    __syncthreads();

    // write phase: each warp writes one l-row of 128 c (256B) per it
#pragma unroll
    for (int it = 0; it < 8; it++) {
        int l = it * 8 + warp;
        __half h0 = tile[lane * 4 + 0][l];
        __half h1 = tile[lane * 4 + 1][l];
        __half h2 = tile[lane * 4 + 2][l];
        __half h3 = tile[lane * 4 + 3][l];
        half2 p0 = __halves2half2(h0, h1);
        half2 p1 = __halves2half2(h2, h3);
        uint2 w;
        w.x = *reinterpret_cast<uint32_t*>(&p0);
        w.y = *reinterpret_cast<uint32_t*>(&p1);
        *reinterpret_cast<uint2*>(
            &g_qx[((size_t)b * LPAD + l0 + l + 1) * CIN + c0 + lane * 4]) = w;
    }
}

// ---------------- kernel 4: 3-stage pipelined mma.sync GEMM-conv, 2 CTAs/SM ----------------
// out[b, o0+m, L0+n] = sum over (k, c) of qx[b, L0+n+k-1, c] * w''[o0+m, c, k]  (+bias)
__global__ void __launch_bounds__(256, 2)
qconv_gemm(const float* __restrict__ bias, float* __restrict__ out) {
    extern __shared__ __align__(16) char smem[];
    const uint32_t sbase = smem_u32(smem);
    const int tid  = threadIdx.x;
    const int wid  = tid >> 5;
    const int lane = tid & 31;
    const int L0 = blockIdx.x * TILE_N;
    const int o0 = blockIdx.y * TILE_M;
    const int b  = blockIdx.z;

    // warp tile: 32(m) x 64(n); warp grid 4(m) x 2(n)
    const int wm = (wid & 3) * 32;
    const int wn = (wid >> 2) * 64;

    const uint4* gw = reinterpret_cast<const uint4*>(g_w2);
    const uint4* gx = reinterpret_cast<const uint4*>(g_qx);

    // ---- async tile loader: 16B per cp.async, swizzled ----
    auto load_chunk = [&](int chunk, int stage) {
        const int k  = chunk >> 3;      // tap 0..2
        const int cc = chunk & 7;       // c-chunk 0..7
        const uint32_t sb = sbase + stage * STAGE_BYTES;
        // A tile: 128 rows x 8 units -> 1024 units, 4 per thread
#pragma unroll
        for (int j = 0; j < 4; j++) {
            int e = tid + j * 256;
            int r = e >> 3, u = e & 7;
            uint32_t so = (uint32_t)(r * 128) + SWU(u, r);
            cp_async16(sb + A_OFF + so, &gw[(size_t)(k * COUT + o0 + r) * 64 + cc * 8 + u]);
        }
        // B tile: 128 rows x 8 units -> 1024 units, 4 per thread
#pragma unroll
        for (int j = 0; j < 4; j++) {
            int e = tid + j * 256;
            int r = e >> 3, u = e & 7;
            uint32_t so = (uint32_t)(r * 128) + SWU(u, r);
            cp_async16(sb + B_OFF + so, &gx[((size_t)b * LPAD + L0 + k + r) * 64 + cc * 8 + u]);
        }
    };

    float acc[2][8][4];
#pragma unroll
    for (int mi = 0; mi < 2; mi++)
#pragma unroll
        for (int nj = 0; nj < 8; nj++)
#pragma unroll
            for (int q = 0; q < 4; q++) acc[mi][nj][q] = 0.f;

    // prologue: 2 stages in flight
    load_chunk(0, 0); CP_COMMIT();
    load_chunk(1, 1); CP_COMMIT();

    // ldmatrix lane addressing
    const int lrow = (lane & 7) + ((lane >> 3) & 1) * 8;   // row within 16-row block
    const int lcol = (lane >> 4);                          // 0/1 -> +16B (k+8)

    for (int i = 0; i < NCHUNK; i++) {
        CP_WAIT(1);                    // chunk i resident; chunk i+1 may still be in flight
        __syncthreads();
        if (i + 2 < NCHUNK) { load_chunk(i + 2, (i + 2) % NSTAGE); CP_COMMIT(); }

        const uint32_t sb = sbase + (i % NSTAGE) * STAGE_BYTES;
#pragma unroll
        for (int ks = 0; ks < 4; ks++) {
            // B fragments: 4 x ldmatrix.x4 covering 64 n x 16 k
            uint32_t bf[4][4];
#pragma unroll
            for (int t = 0; t < 4; t++) {
                int r = wn + t * 16 + lrow;
                int u = ks * 2 + lcol;
                ldm_x4(bf[t][0], bf[t][1], bf[t][2], bf[t][3],
                       sb + B_OFF + r * 128 + SWU(u, r));
            }
            // A fragments + MMA
            uint32_t af[2][4];
#pragma unroll
            for (int t = 0; t < 2; t++) {
                int r = wm + t * 16 + lrow;
                int u = ks * 2 + lcol;
                ldm_x4(af[t][0], af[t][1], af[t][2], af[t][3],
                       sb + A_OFF + r * 128 + SWU(u, r));
            }
#pragma unroll
            for (int mi = 0; mi < 2; mi++)
#pragma unroll
                for (int t = 0; t < 4; t++) {
                    mma16816(acc[mi][t*2  ][0], acc[mi][t*2  ][1], acc[mi][t*2  ][2], acc[mi][t*2  ][3],
                             af[mi][0], af[mi][1], af[mi][2], af[mi][3], bf[t][0], bf[t][2]);
                    mma16816(acc[mi][t*2+1][0], acc[mi][t*2+1][1], acc[mi][t*2+1][2], acc[mi][t*2+1][3],
                             af[mi][0], af[mi][1], af[mi][2], af[mi][3], bf[t][1], bf[t][3]);
                }
        }
    }

    // ---- epilogue: bias + store ----
#pragma unroll
    for (int mi = 0; mi < 2; mi++) {
        int r0 = wm + mi * 16 + (lane >> 2);
        int o_a = o0 + r0, o_b = o0 + r0 + 8;
        float bv0 = bias[o_a], bv1 = bias[o_b];
        float* pa = out + ((size_t)b * COUT + o_a) * QL + L0;
        float* pb = out + ((size_t)b * COUT + o_b) * QL + L0;
#pragma unroll
        for (int nj = 0; nj < 8; nj++) {
            int col = wn + nj * 8 + (lane & 3) * 2;
            float2 v0 = make_float2(acc[mi][nj][0] + bv0, acc[mi][nj][1] + bv0);
            float2 v1 = make_float2(acc[mi][nj][2] + bv1, acc[mi][nj][3] + bv1);
            *reinterpret_cast<float2*>(pa + col) = v0;
            *reinterpret_cast<float2*>(pb + col) = v1;
        }
    }
}

// ---------------- launch ----------------
extern "C" void kernel_launch(void* const* d_in, const int* in_sizes, int n_in,
                              void* d_out, int out_size) {
    (void)in_sizes; (void)n_in; (void)out_size;
    const float* x       = (const float*)d_in[0];
    const float* weight  = (const float*)d_in[1];
    const float* bias    = (const float*)d_in[2];
    const float* a_scale = (const float*)d_in[3];
    const float* w_scale = (const float*)d_in[4];
    float* out = (float*)d_out;

    prep_w_kernel<<<COUT, CIN>>>(weight, a_scale, w_scale);
    pad_kernel<<<BATCH, CIN>>>();
    quant_kernel<<<dim3(QL / 64, CIN / 128, BATCH), 256>>>(x, a_scale);

    cudaFuncSetAttribute(qconv_gemm, cudaFuncAttributeMaxDynamicSharedMemorySize, SMEM_DYN);
    qconv_gemm<<<dim3(QL / TILE_N, COUT / TILE_M, BATCH), 256, SMEM_DYN>>>(bias, out);
}